// round 1
// baseline (speedup 1.0000x reference)
#include <cuda_runtime.h>
#include <cstdint>

#define DIN   128
#define DOUT  128
#define TILE_M 128
#define THREADS 512
#define ROWPAD 132          // floats per x-row in smem (bank-spread + 16B aligned)
#define NK2    64           // 128 k / 2 (k-paired)
#define REDSTR 20           // reduction row stride (floats)

// ---- smem layout (dynamic) ----
// sX0 [128*132] f32, sX1 [128*132] f32      (double-buffered X tiles)
// sw2 [64][128] u64                          (W, k-paired, slot-permuted)
// redA[128*20] f32, redB[128*20] f32         (per-row partial reductions)
// xn2s[128], coefA[128], coefB[128], sbias[128], sb2[1]
#define SX_ELEMS   (TILE_M * ROWPAD)
#define SW2_U64    (NK2 * 128)
#define SMEM_BYTES (2*SX_ELEMS*4 + SW2_U64*8 + 2*128*REDSTR*4 + (128*4 + 1)*4)

__device__ __forceinline__ unsigned smem_u32(const void* p) {
    return (unsigned)__cvta_generic_to_shared(p);
}
__device__ __forceinline__ void cp_async16(unsigned dst, const void* src) {
    asm volatile("cp.async.ca.shared.global [%0], [%1], 16;\n" :: "r"(dst), "l"(src));
}
__device__ __forceinline__ void cp_commit() { asm volatile("cp.async.commit_group;\n"); }
__device__ __forceinline__ void cp_wait0()  { asm volatile("cp.async.wait_group 0;\n"); }

// Blackwell packed fp32x2 FMA: lo/hi lanes accumulate even/odd-k partial sums.
__device__ __forceinline__ unsigned long long ffma2(unsigned long long a,
                                                    unsigned long long b,
                                                    unsigned long long c) {
    unsigned long long d;
    asm("fma.rn.f32x2 %0, %1, %2, %3;" : "=l"(d) : "l"(a), "l"(b), "l"(c));
    return d;
}

extern "C" __global__ void __launch_bounds__(THREADS, 1)
mobius_linear_kernel(const float* __restrict__ X,
                     const float* __restrict__ W,
                     const float* __restrict__ bias,
                     float* __restrict__ out,
                     int nrows)
{
    extern __shared__ char smem_raw[];
    float* sX0 = (float*)smem_raw;
    float* sX1 = sX0 + SX_ELEMS;
    unsigned long long* sw2 = (unsigned long long*)(sX1 + SX_ELEMS);
    float* redA  = (float*)(sw2 + SW2_U64);
    float* redB  = redA + 128 * REDSTR;
    float* xn2s  = redB + 128 * REDSTR;
    float* coefA = xn2s + 128;
    float* coefB = coefA + 128;
    float* sbias = coefB + 128;
    float* sb2   = sbias + 128;

    const int tid = threadIdx.x;
    const int tx  = tid & 15;   // output-col group: cols tx*8 .. tx*8+7
    const int ty  = tid >> 4;   // row group: rows ty*4 .. ty*4+3

    if (tid < 128) sbias[tid] = bias[tid];

    // ---- Build sw2 once: u64 = (W[j][2k2], W[j][2k2+1]) at slot-permuted position.
    // Logical 16B-slot s (pair of cols {2s,2s+1}) -> physical slot phi(s)=((s&3)<<4)|(s>>2)
    // so that reader lanes (tx) hit consecutive 16B slots -> conflict-free LDS.128.
    #pragma unroll
    for (int i = 0; i < 16; i++) {
        int id = tid + THREADS * i;          // 0..8191 over (k2, phys u64 p)
        int k2 = id >> 7;
        int p  = id & 127;                   // physical u64 index within row
        int phs = p >> 1;                    // physical 16B slot
        int s   = (phs >> 4) + ((phs & 15) << 2);  // inverse permutation
        int j   = 2 * s + (p & 1);           // logical output column
        float2 w = *(const float2*)(W + j * DIN + 2 * k2);
        unsigned long long v = (unsigned long long)__float_as_uint(w.x)
                             | ((unsigned long long)__float_as_uint(w.y) << 32);
        sw2[k2 * 128 + p] = v;               // consecutive p -> conflict-free STS
    }
    __syncthreads();

    // ---- b2 = ||bias||^2 (once)
    if (tid < 32) {
        float s = 0.f;
        #pragma unroll
        for (int i = 0; i < 4; i++) { float v = sbias[tid + 32 * i]; s = fmaf(v, v, s); }
        #pragma unroll
        for (int o = 16; o; o >>= 1) s += __shfl_xor_sync(0xffffffffu, s, o);
        if (tid == 0) *sb2 = s;
    }
    __syncthreads();

    const int ntiles = nrows / TILE_M;
    int tile = blockIdx.x;

    // ---- prefetch first tile into buf0
    if (tile < ntiles) {
        const float* src = X + (long long)tile * TILE_M * DIN;
        #pragma unroll
        for (int i = 0; i < 8; i++) {
            int f = tid + THREADS * i;       // 0..4095 float4s
            int b = f >> 5, k4 = f & 31;
            cp_async16(smem_u32(sX0 + b * ROWPAD + k4 * 4), src + b * DIN + k4 * 4);
        }
    }
    cp_commit();

    int buf = 0;
    for (; tile < ntiles; tile += gridDim.x) {
        float* cur = buf ? sX1 : sX0;
        float* nxt = buf ? sX0 : sX1;

        cp_wait0();
        __syncthreads();   // cur ready; prior iteration fully done -> safe to refill nxt

        // ---- prefetch next tile
        int tnext = tile + gridDim.x;
        if (tnext < ntiles) {
            const float* src = X + (long long)tnext * TILE_M * DIN;
            #pragma unroll
            for (int i = 0; i < 8; i++) {
                int f = tid + THREADS * i;
                int b = f >> 5, k4 = f & 31;
                cp_async16(smem_u32(nxt + b * ROWPAD + k4 * 4), src + b * DIN + k4 * 4);
            }
        }
        cp_commit();

        // ---- x_norm^2 per row (strided k -> conflict-free), 4 lanes/row + shfl
        {
            int r = tid >> 2, q = tid & 3;
            const float* row = cur + r * ROWPAD;
            float s = 0.f;
            #pragma unroll
            for (int kk = 0; kk < 32; kk++) {
                float v = row[q + 4 * kk];
                s = fmaf(v, v, s);
            }
            s += __shfl_xor_sync(0xffffffffu, s, 1);
            s += __shfl_xor_sync(0xffffffffu, s, 2);
            if (q == 0) xn2s[r] = s;
        }

        // ---- GEMM: 4x8 microtile, k-paired f32x2 accumulators
        unsigned long long acc[4][8];
        #pragma unroll
        for (int i = 0; i < 4; i++)
            #pragma unroll
            for (int j = 0; j < 8; j++) acc[i][j] = 0ULL;

        const float* arow = cur + (ty * 4) * ROWPAD;
        // reader physical slot for (tx, jp): phi = (jp<<4) | tx
        const unsigned long long* brow = sw2;
        #pragma unroll 4
        for (int k2 = 0; k2 < NK2; k2++) {
            unsigned long long a2[4], b2v[8];
            #pragma unroll
            for (int i = 0; i < 4; i++)
                a2[i] = *(const unsigned long long*)(arow + i * ROWPAD + 2 * k2);
            #pragma unroll
            for (int jp = 0; jp < 4; jp++) {
                ulonglong2 t = *(const ulonglong2*)(brow + k2 * 128 + (((jp << 4) | tx) << 1));
                b2v[2 * jp]     = t.x;
                b2v[2 * jp + 1] = t.y;
            }
            #pragma unroll
            for (int i = 0; i < 4; i++)
                #pragma unroll
                for (int j = 0; j < 8; j++)
                    acc[i][j] = ffma2(a2[i], b2v[j], acc[i][j]);
        }

        // ---- finish Mx (lo+hi), local reductions over this thread's 8 cols
        float bb[8];
        #pragma unroll
        for (int j = 0; j < 8; j++) bb[j] = sbias[tx * 8 + j];

        float m[4][8];
        #pragma unroll
        for (int i = 0; i < 4; i++) {
            float s2 = 0.f, sb = 0.f;
            #pragma unroll
            for (int j = 0; j < 8; j++) {
                float lo = __uint_as_float((unsigned)acc[i][j]);
                float hi = __uint_as_float((unsigned)(acc[i][j] >> 32));
                float v = lo + hi;
                m[i][j] = v;
                s2 = fmaf(v, v, s2);
                sb = fmaf(v, bb[j], sb);
            }
            int r = ty * 4 + i;
            redA[r * REDSTR + tx] = s2;
            redB[r * REDSTR + tx] = sb;
        }
        __syncthreads();

        // ---- per-row scalar math -> out = A*Mx + B*bias (projx folded in)
        if (tid < 128) {
            int r = tid;
            const float4* pa = (const float4*)(redA + r * REDSTR);
            const float4* pb = (const float4*)(redB + r * REDSTR);
            float mxn2 = 0.f, dotb = 0.f;
            #pragma unroll
            for (int i = 0; i < 4; i++) {
                float4 a = pa[i]; mxn2 += (a.x + a.y) + (a.z + a.w);
                float4 b = pb[i]; dotb += (b.x + b.y) + (b.z + b.w);
            }
            float b2c = *sb2;
            float xn  = fmaxf(sqrtf(xn2s[r]), 1e-15f);
            float mxn = fmaxf(sqrtf(mxn2),   1e-15f);
            float u   = fminf(xn, 1.0f - 1e-7f);
            float at  = 0.5f * (log1pf(u) - log1pf(-u));
            float s   = tanhf(mxn / xn * at) / mxn;
            if (mxn <= 1e-10f) s = 0.0f;            // where(Mx_norm<=1e-10, 0, res)
            float xy    = s * dotb;                 // <y, bias>
            float y2    = s * s * mxn2;             // ||y||^2
            float alpha = 1.0f + 2.0f * xy + b2c;
            float beta  = 1.0f - y2;
            float den   = fmaxf(1.0f + 2.0f * xy + y2 * b2c, 1e-15f);
            float A  = s * alpha / den;
            float Bc = beta / den;
            float o2 = A * A * mxn2 + 2.0f * A * Bc * dotb + Bc * Bc * b2c;
            float on = fmaxf(sqrtf(o2), 1e-15f);
            float mx = 1.0f - 1e-5f;                // maxnorm
            float f  = (on > mx) ? (mx / on) : 1.0f;
            coefA[r] = A * f;
            coefB[r] = Bc * f;
        }
        __syncthreads();

        // ---- write outputs (coalesced float4)
        float* orow = out + (long long)tile * TILE_M * DOUT;
        #pragma unroll
        for (int i = 0; i < 4; i++) {
            int r = ty * 4 + i;
            float A = coefA[r], Bc = coefB[r];
            float4 v0, v1;
            v0.x = fmaf(A, m[i][0], Bc * bb[0]);
            v0.y = fmaf(A, m[i][1], Bc * bb[1]);
            v0.z = fmaf(A, m[i][2], Bc * bb[2]);
            v0.w = fmaf(A, m[i][3], Bc * bb[3]);
            v1.x = fmaf(A, m[i][4], Bc * bb[4]);
            v1.y = fmaf(A, m[i][5], Bc * bb[5]);
            v1.z = fmaf(A, m[i][6], Bc * bb[6]);
            v1.w = fmaf(A, m[i][7], Bc * bb[7]);
            *(float4*)(orow + r * DOUT + tx * 8)     = v0;
            *(float4*)(orow + r * DOUT + tx * 8 + 4) = v1;
        }

        buf ^= 1;
    }
}

extern "C" void kernel_launch(void* const* d_in, const int* in_sizes, int n_in,
                              void* d_out, int out_size) {
    const float* X    = (const float*)d_in[0];
    const float* W    = (const float*)d_in[1];
    const float* bias = (const float*)d_in[2];
    float* out = (float*)d_out;

    int nrows = in_sizes[0] / DIN;

    cudaFuncSetAttribute(mobius_linear_kernel,
                         cudaFuncAttributeMaxDynamicSharedMemorySize, SMEM_BYTES);

    int nsm = 148;
    cudaDeviceGetAttribute(&nsm, cudaDevAttrMultiProcessorCount, 0);
    int ntiles = nrows / TILE_M;
    int grid = nsm < ntiles ? nsm : ntiles;

    mobius_linear_kernel<<<grid, THREADS, SMEM_BYTES>>>(X, W, bias, out, nrows);
}